// round 1
// baseline (speedup 1.0000x reference)
#include <cuda_runtime.h>

// Problem constants
constexpr int B   = 32768;
constexpr int F   = 200;
constexpr int DI  = 5;
constexpr int H   = 15;   // padded to 16 in smem
constexpr int OC  = 30;   // padded to 32 in smem
constexpr int FC  = 8;            // features per smem chunk
constexpr int NCH = F / FC;       // 25 chunks

constexpr int TPB     = 256;
constexpr int GRID    = 148;                       // one block per SM
constexpr int ROWS_PB = (B + GRID - 1) / GRID;     // 222

// Padded smem layouts (floats)
constexpr int W1S_F = FC * 5 * 16;    // [f][d][16]
constexpr int B1S_F = FC * 16;        // [f][16]
constexpr int W2S_F = FC * 15 * 32;   // [f][h][32]
constexpr int B2S_F = FC * 32;        // [f][32]
constexpr int W3S_F = FC * 32;        // [f][32]

__global__ __launch_bounds__(TPB, 1)
void mlp_fused_kernel(const float* __restrict__ y,
                      const float* __restrict__ W1,
                      const float* __restrict__ b1,
                      const float* __restrict__ W2,
                      const float* __restrict__ b2,
                      const float* __restrict__ W3,
                      const float* __restrict__ b3,
                      float* __restrict__ out)
{
    __shared__ float w1s[W1S_F];
    __shared__ float b1s[B1S_F];
    __shared__ float w2s[W2S_F];
    __shared__ float b2s[B2S_F];
    __shared__ float w3s[W3S_F];

    const int tid  = threadIdx.x;
    const int r0   = blockIdx.x * ROWS_PB;
    const int row  = r0 + tid;
    const bool valid = (tid < ROWS_PB) && (row < B);
    const int rowc = (row < B) ? row : (B - 1);   // clamp: idle threads redo a row, store suppressed

    const float* __restrict__ yrow = y + (size_t)rowc * (F * DI);

    float acc0 = 0.f, acc1 = 0.f, acc2 = 0.f, acc3 = 0.f;

    for (int c = 0; c < NCH; ++c) {
        const int f0 = c * FC;

        __syncthreads();   // prior chunk's compute done before overwrite

        // ---- cooperative weight staging (coalesced gmem, padded smem) ----
        for (int i = tid; i < FC * 75; i += TPB) {
            int f = i / 75, r = i % 75;
            int d = r / 15, h = r % 15;
            w1s[f * 80 + d * 16 + h] = W1[(f0 + f) * 75 + r];
        }
        for (int i = tid; i < FC * 15; i += TPB) {
            int f = i / 15, h = i % 15;
            b1s[f * 16 + h] = b1[(f0 + f) * 15 + h];
        }
        for (int i = tid; i < FC * 450; i += TPB) {
            int f = i / 450, r = i % 450;
            int h = r / 30, o = r % 30;
            w2s[f * 480 + h * 32 + o] = W2[(f0 + f) * 450 + r];
        }
        for (int i = tid; i < FC * 30; i += TPB) {
            int f = i / 30, o = i % 30;
            b2s[f * 32 + o] = b2[(f0 + f) * 30 + o];
            w3s[f * 32 + o] = W3[(f0 + f) * 30 + o];
        }
        __syncthreads();

        // ---- per-thread compute over this chunk's 8 features ----
        for (int fl = 0; fl < FC; ++fl) {
            // y[row, f, 0..4]: 5 scalar loads; consecutive features are contiguous -> L1 lines fully used
            const float* __restrict__ yf = yrow + (f0 + fl) * DI;
            const float y0 = __ldg(yf + 0);
            const float y1 = __ldg(yf + 1);
            const float y2 = __ldg(yf + 2);
            const float y3 = __ldg(yf + 3);
            const float y4 = __ldg(yf + 4);

            // ---- layer 1: h1[0..14] = b1 + y @ W1[f]   (h1[15] is padding garbage, never consumed)
            float h1[16];
            {
                const float4* b1v = reinterpret_cast<const float4*>(b1s + fl * 16);
                #pragma unroll
                for (int j = 0; j < 4; ++j) {
                    float4 v = b1v[j];
                    h1[4*j+0] = v.x; h1[4*j+1] = v.y; h1[4*j+2] = v.z; h1[4*j+3] = v.w;
                }
            }
            #pragma unroll
            for (int d = 0; d < 5; ++d) {
                const float yd = (d == 0) ? y0 : (d == 1) ? y1 : (d == 2) ? y2 : (d == 3) ? y3 : y4;
                const float4* wv = reinterpret_cast<const float4*>(w1s + fl * 80 + d * 16);
                #pragma unroll
                for (int j = 0; j < 4; ++j) {
                    float4 v = wv[j];
                    h1[4*j+0] = fmaf(yd, v.x, h1[4*j+0]);
                    h1[4*j+1] = fmaf(yd, v.y, h1[4*j+1]);
                    h1[4*j+2] = fmaf(yd, v.z, h1[4*j+2]);
                    h1[4*j+3] = fmaf(yd, v.w, h1[4*j+3]);
                }
            }

            // ---- layer 2: s[0..29] = b2 + h1 @ W2[f]   (s[30..31] padding garbage, never consumed)
            float s[32];
            {
                const float4* b2v = reinterpret_cast<const float4*>(b2s + fl * 32);
                #pragma unroll
                for (int j = 0; j < 8; ++j) {
                    float4 v = b2v[j];
                    s[4*j+0] = v.x; s[4*j+1] = v.y; s[4*j+2] = v.z; s[4*j+3] = v.w;
                }
            }
            #pragma unroll
            for (int h = 0; h < 15; ++h) {
                const float hh = h1[h];
                const float4* wv = reinterpret_cast<const float4*>(w2s + fl * 480 + h * 32);
                #pragma unroll
                for (int j = 0; j < 8; ++j) {
                    float4 v = wv[j];
                    s[4*j+0] = fmaf(hh, v.x, s[4*j+0]);
                    s[4*j+1] = fmaf(hh, v.y, s[4*j+1]);
                    s[4*j+2] = fmaf(hh, v.z, s[4*j+2]);
                    s[4*j+3] = fmaf(hh, v.w, s[4*j+3]);
                }
            }

            // ---- relu + dot with w3 slice (o = 0..29), 4 parallel accumulators
            const float4* w3v = reinterpret_cast<const float4*>(w3s + fl * 32);
            #pragma unroll
            for (int j = 0; j < 7; ++j) {
                float4 v = w3v[j];
                acc0 = fmaf(fmaxf(s[4*j+0], 0.f), v.x, acc0);
                acc1 = fmaf(fmaxf(s[4*j+1], 0.f), v.y, acc1);
                acc2 = fmaf(fmaxf(s[4*j+2], 0.f), v.z, acc2);
                acc3 = fmaf(fmaxf(s[4*j+3], 0.f), v.w, acc3);
            }
            {   // o = 28, 29 only
                float4 v = w3v[7];
                acc0 = fmaf(fmaxf(s[28], 0.f), v.x, acc0);
                acc1 = fmaf(fmaxf(s[29], 0.f), v.y, acc1);
            }
        }
    }

    if (valid) {
        out[row] = (acc0 + acc1) + (acc2 + acc3) + __ldg(b3);
    }
}

extern "C" void kernel_launch(void* const* d_in, const int* in_sizes, int n_in,
                              void* d_out, int out_size)
{
    const float* y  = (const float*)d_in[0];
    const float* W1 = (const float*)d_in[1];
    const float* b1 = (const float*)d_in[2];
    const float* W2 = (const float*)d_in[3];
    const float* b2 = (const float*)d_in[4];
    const float* W3 = (const float*)d_in[5];
    const float* b3 = (const float*)d_in[6];
    mlp_fused_kernel<<<GRID, TPB>>>(y, W1, b1, W2, b2, W3, b3, (float*)d_out);
}

// round 2
// speedup vs baseline: 1.0088x; 1.0088x over previous
#include <cuda_runtime.h>

// Problem constants
constexpr int B   = 32768;
constexpr int F   = 200;
constexpr int DI  = 5;
constexpr int FC  = 8;            // features per smem chunk
constexpr int NCH = F / FC;       // 25 chunks

constexpr int TPB   = 128;
constexpr int GRID  = 148;
constexpr int NTHR  = GRID * TPB;   // 18944 threads, 2 rows each -> 37888 slots >= 32768

// Padded smem layouts (floats)
constexpr int W1S_F = FC * 5 * 16;    // [f][d][16]
constexpr int B1S_F = FC * 16;        // [f][16]
constexpr int W2S_F = FC * 15 * 32;   // [f][h][32]
constexpr int B2S_F = FC * 32;        // [f][32]
constexpr int W3S_F = FC * 32;        // [f][32]

// ---- packed f32x2 helpers (Blackwell; ptxas never auto-fuses these) ----
__device__ __forceinline__ unsigned long long pack2(float lo, float hi) {
    unsigned long long r;
    asm("mov.b64 %0, {%1, %2};" : "=l"(r) : "f"(lo), "f"(hi));
    return r;
}
__device__ __forceinline__ void unpack2(unsigned long long v, float& lo, float& hi) {
    asm("mov.b64 {%0, %1}, %2;" : "=f"(lo), "=f"(hi) : "l"(v));
}
__device__ __forceinline__ void fma2(unsigned long long& d, unsigned long long a, unsigned long long b) {
    asm("fma.rn.f32x2 %0, %1, %2, %0;" : "+l"(d) : "l"(a), "l"(b));
}

__global__ __launch_bounds__(TPB, 1)
void mlp_fused_kernel(const float* __restrict__ y,
                      const float* __restrict__ W1,
                      const float* __restrict__ b1,
                      const float* __restrict__ W2,
                      const float* __restrict__ b2,
                      const float* __restrict__ W3,
                      const float* __restrict__ b3,
                      float* __restrict__ out)
{
    __shared__ float w1s[W1S_F];
    __shared__ float b1s[B1S_F];
    __shared__ float w2s[W2S_F];
    __shared__ float b2s[B2S_F];
    __shared__ float w3s[W3S_F];

    const int tid  = threadIdx.x;
    const int gtid = blockIdx.x * TPB + tid;          // 0..18943, always < B
    const int rowA = gtid;
    const int rowBr = gtid + NTHR;                    // 18944..37887
    const bool validB = (rowBr < B);
    const int rowB = validB ? rowBr : (B - 1);        // clamp: redundant recompute, store suppressed

    const float* __restrict__ yA = y + (size_t)rowA * (F * DI);
    const float* __restrict__ yB = y + (size_t)rowB * (F * DI);

    float accA0 = 0.f, accA1 = 0.f, accB0 = 0.f, accB1 = 0.f;

    for (int c = 0; c < NCH; ++c) {
        const int f0 = c * FC;

        __syncthreads();

        // ---- cooperative weight staging ----
        for (int i = tid; i < FC * 75; i += TPB) {
            int f = i / 75, r = i % 75;
            int d = r / 15, h = r % 15;
            w1s[f * 80 + d * 16 + h] = W1[(f0 + f) * 75 + r];
        }
        for (int i = tid; i < FC * 15; i += TPB) {
            int f = i / 15, h = i % 15;
            b1s[f * 16 + h] = b1[(f0 + f) * 15 + h];
        }
        for (int i = tid; i < FC * 450; i += TPB) {
            int f = i / 450, r = i % 450;
            int h = r / 30, o = r % 30;
            w2s[f * 480 + h * 32 + o] = W2[(f0 + f) * 450 + r];
        }
        for (int i = tid; i < FC * 30; i += TPB) {
            int f = i / 30, o = i % 30;
            b2s[f * 32 + o] = b2[(f0 + f) * 30 + o];
            w3s[f * 32 + o] = W3[(f0 + f) * 30 + o];
        }
        __syncthreads();

        for (int fl = 0; fl < FC; ++fl) {
            const float* __restrict__ yfA = yA + (f0 + fl) * DI;
            const float* __restrict__ yfB = yB + (f0 + fl) * DI;

            // packed broadcast multipliers for layer 1
            unsigned long long ydA[5], ydB[5];
            #pragma unroll
            for (int d = 0; d < 5; ++d) {
                float va = __ldg(yfA + d);
                float vb = __ldg(yfB + d);
                ydA[d] = pack2(va, va);
                ydB[d] = pack2(vb, vb);
            }

            // ---- layer 1 (packed): h1[0..14], pair 7 hi = padding garbage ----
            unsigned long long h1A[8], h1B[8];
            {
                const ulonglong2* bv = reinterpret_cast<const ulonglong2*>(b1s + fl * 16);
                #pragma unroll
                for (int j = 0; j < 4; ++j) {
                    ulonglong2 v = bv[j];
                    h1A[2*j]   = v.x; h1A[2*j+1] = v.y;
                    h1B[2*j]   = v.x; h1B[2*j+1] = v.y;
                }
            }
            #pragma unroll
            for (int d = 0; d < 5; ++d) {
                const ulonglong2* wv = reinterpret_cast<const ulonglong2*>(w1s + fl * 80 + d * 16);
                #pragma unroll
                for (int j = 0; j < 4; ++j) {
                    ulonglong2 v = wv[j];
                    fma2(h1A[2*j],   v.x, ydA[d]);
                    fma2(h1A[2*j+1], v.y, ydA[d]);
                    fma2(h1B[2*j],   v.x, ydB[d]);
                    fma2(h1B[2*j+1], v.y, ydB[d]);
                }
            }

            // unpack h1 pairs -> scalar multipliers (hi of pair 7 unused)
            float hA[16], hB[16];
            #pragma unroll
            for (int j = 0; j < 8; ++j) {
                unpack2(h1A[j], hA[2*j], hA[2*j+1]);
                unpack2(h1B[j], hB[2*j], hB[2*j+1]);
            }

            // ---- layer 2 (packed): 16 f32x2 accumulators per row (outputs 30,31 = padding) ----
            unsigned long long sA[16], sB[16];
            {
                const ulonglong2* bv = reinterpret_cast<const ulonglong2*>(b2s + fl * 32);
                #pragma unroll
                for (int j = 0; j < 8; ++j) {
                    ulonglong2 v = bv[j];
                    sA[2*j]   = v.x; sA[2*j+1] = v.y;
                    sB[2*j]   = v.x; sB[2*j+1] = v.y;
                }
            }
            #pragma unroll
            for (int h = 0; h < 15; ++h) {
                unsigned long long hhA = pack2(hA[h], hA[h]);
                unsigned long long hhB = pack2(hB[h], hB[h]);
                const ulonglong2* wv = reinterpret_cast<const ulonglong2*>(w2s + fl * 480 + h * 32);
                #pragma unroll
                for (int j = 0; j < 8; ++j) {
                    ulonglong2 v = wv[j];
                    fma2(sA[2*j],   v.x, hhA);
                    fma2(sA[2*j+1], v.y, hhA);
                    fma2(sB[2*j],   v.x, hhB);
                    fma2(sB[2*j+1], v.y, hhB);
                }
            }

            // ---- relu + dot with w3 slice (outputs 0..29) ----
            const float4* w3v = reinterpret_cast<const float4*>(w3s + fl * 32);
            #pragma unroll
            for (int j = 0; j < 7; ++j) {           // pairs 2j..2j+1 -> outputs 4j..4j+3
                float4 v = w3v[j];
                float a0, a1, a2, a3, b0, b1_, b2_, b3_;
                unpack2(sA[2*j],   a0, a1);
                unpack2(sA[2*j+1], a2, a3);
                unpack2(sB[2*j],   b0, b1_);
                unpack2(sB[2*j+1], b2_, b3_);
                accA0 = fmaf(fmaxf(a0, 0.f), v.x, accA0);
                accA1 = fmaf(fmaxf(a1, 0.f), v.y, accA1);
                accA0 = fmaf(fmaxf(a2, 0.f), v.z, accA0);
                accA1 = fmaf(fmaxf(a3, 0.f), v.w, accA1);
                accB0 = fmaf(fmaxf(b0,  0.f), v.x, accB0);
                accB1 = fmaf(fmaxf(b1_, 0.f), v.y, accB1);
                accB0 = fmaf(fmaxf(b2_, 0.f), v.z, accB0);
                accB1 = fmaf(fmaxf(b3_, 0.f), v.w, accB1);
            }
            {   // outputs 28, 29 (pair 14); pair 15 is padding
                float4 v = w3v[7];
                float a0, a1, b0, b1_;
                unpack2(sA[14], a0, a1);
                unpack2(sB[14], b0, b1_);
                accA0 = fmaf(fmaxf(a0, 0.f), v.x, accA0);
                accA1 = fmaf(fmaxf(a1, 0.f), v.y, accA1);
                accB0 = fmaf(fmaxf(b0,  0.f), v.x, accB0);
                accB1 = fmaf(fmaxf(b1_, 0.f), v.y, accB1);
            }
        }
    }

    const float bias3 = __ldg(b3);
    out[rowA] = accA0 + accA1 + bias3;
    if (validB) out[rowBr] = accB0 + accB1 + bias3;
}

extern "C" void kernel_launch(void* const* d_in, const int* in_sizes, int n_in,
                              void* d_out, int out_size)
{
    const float* y  = (const float*)d_in[0];
    const float* W1 = (const float*)d_in[1];
    const float* b1 = (const float*)d_in[2];
    const float* W2 = (const float*)d_in[3];
    const float* b2 = (const float*)d_in[4];
    const float* W3 = (const float*)d_in[5];
    const float* b3 = (const float*)d_in[6];
    mlp_fused_kernel<<<GRID, TPB>>>(y, W1, b1, W2, b2, W3, b3, (float*)d_out);
}

// round 3
// speedup vs baseline: 1.3873x; 1.3751x over previous
#include <cuda_runtime.h>

// Problem constants
constexpr int B    = 32768;
constexpr int FTOT = 200;
constexpr int S    = 2;            // feature split (halves)
constexpr int FH   = FTOT / S;     // 100 features per half
constexpr int FC   = 10;           // features per smem chunk
constexpr int NCH  = FH / FC;      // 10 chunks per half

constexpr int TPB       = 256;
constexpr int RBLK      = 64;              // row-blocks per half
constexpr int GRID      = S * RBLK;        // 128 blocks
constexpr int HALF_ROWS = RBLK * TPB;      // 16384 (R=2: rowB = rowA + 16384)

constexpr int YPITCH = 53;                 // 50 data floats + pad; odd -> conflict-free LDS

// dynamic smem layout (float offsets; all 16B-aligned where vector-read)
constexpr int OFF_YA = 0;
constexpr int OFF_YB = OFF_YA + TPB * YPITCH;        // 13568
constexpr int OFF_W1 = OFF_YB + TPB * YPITCH;        // 27136  [f][d][16]
constexpr int OFF_B1 = OFF_W1 + FC * 5 * 16;         // 27936  [f][16]
constexpr int OFF_W2 = OFF_B1 + FC * 16;             // 28096  [f][h][32]
constexpr int OFF_B2 = OFF_W2 + FC * 15 * 32;        // 32896  [f][32]
constexpr int OFF_W3 = OFF_B2 + FC * 32;             // 33216  [f][32]
constexpr int SMEM_FLOATS = OFF_W3 + FC * 32;        // 33536
constexpr int SMEM_BYTES  = SMEM_FLOATS * 4;         // 134144 B

// ---- packed f32x2 helpers ----
__device__ __forceinline__ unsigned long long pack2(float lo, float hi) {
    unsigned long long r;
    asm("mov.b64 %0, {%1, %2};" : "=l"(r) : "f"(lo), "f"(hi));
    return r;
}
__device__ __forceinline__ void unpack2(unsigned long long v, float& lo, float& hi) {
    asm("mov.b64 {%0, %1}, %2;" : "=f"(lo), "=f"(hi) : "l"(v));
}
__device__ __forceinline__ void fma2(unsigned long long& d, unsigned long long a, unsigned long long b) {
    asm("fma.rn.f32x2 %0, %1, %2, %0;" : "+l"(d) : "l"(a), "l"(b));
}

__global__ void init_out_kernel(const float* __restrict__ b3, float* __restrict__ out) {
    int i = blockIdx.x * blockDim.x + threadIdx.x;   // grid covers exactly B
    out[i] = __ldg(b3);
}

__global__ __launch_bounds__(TPB, 1)
void mlp_fused_kernel(const float* __restrict__ y,
                      const float* __restrict__ W1,
                      const float* __restrict__ b1,
                      const float* __restrict__ W2,
                      const float* __restrict__ b2,
                      const float* __restrict__ W3,
                      float* __restrict__ out)
{
    extern __shared__ float smem[];

    const int tid = threadIdx.x;
    const int bh  = blockIdx.x >> 6;          // feature half: 0 or 1
    const int br  = blockIdx.x & 63;          // row block within half

    const int rA0  = br * TPB;
    const int rB0  = rA0 + HALF_ROWS;
    const int rowA = rA0 + tid;               // < 16384
    const int rowB = rB0 + tid;               // < 32768

    float accA0 = 0.f, accA1 = 0.f, accB0 = 0.f, accB1 = 0.f;

    for (int c = 0; c < NCH; ++c) {
        const int f0 = bh * FH + c * FC;

        __syncthreads();

        // ---- stage y tiles (coalesced-ish 200B row segments) ----
        for (int i = tid; i < TPB * 50; i += TPB) {
            int r = i / 50, cc = i % 50;
            smem[OFF_YA + r * YPITCH + cc] = __ldg(y + (size_t)(rA0 + r) * 1000 + f0 * 5 + cc);
            smem[OFF_YB + r * YPITCH + cc] = __ldg(y + (size_t)(rB0 + r) * 1000 + f0 * 5 + cc);
        }
        // ---- stage weights (padded layouts) ----
        for (int i = tid; i < FC * 75; i += TPB) {
            int f = i / 75, r = i % 75;
            int d = r / 15, h = r % 15;
            smem[OFF_W1 + f * 80 + d * 16 + h] = W1[(f0 + f) * 75 + r];
        }
        for (int i = tid; i < FC * 15; i += TPB) {
            int f = i / 15, h = i % 15;
            smem[OFF_B1 + f * 16 + h] = b1[(f0 + f) * 15 + h];
        }
        for (int i = tid; i < FC * 450; i += TPB) {
            int f = i / 450, r = i % 450;
            int h = r / 30, o = r % 30;
            smem[OFF_W2 + f * 480 + h * 32 + o] = W2[(f0 + f) * 450 + r];
        }
        for (int i = tid; i < FC * 30; i += TPB) {
            int f = i / 30, o = i % 30;
            smem[OFF_B2 + f * 32 + o] = b2[(f0 + f) * 30 + o];
            smem[OFF_W3 + f * 32 + o] = W3[(f0 + f) * 30 + o];
        }
        __syncthreads();

        for (int fl = 0; fl < FC; ++fl) {
            // y from smem: conflict-free (pitch 53 odd)
            const float* yAp = &smem[OFF_YA + tid * YPITCH + fl * 5];
            const float* yBp = &smem[OFF_YB + tid * YPITCH + fl * 5];
            unsigned long long ydA[5], ydB[5];
            #pragma unroll
            for (int d = 0; d < 5; ++d) {
                float va = yAp[d], vb = yBp[d];
                ydA[d] = pack2(va, va);
                ydB[d] = pack2(vb, vb);
            }

            // ---- layer 1 (packed): h1[0..14]; pair-7 hi = padding garbage, never consumed ----
            unsigned long long h1A[8], h1B[8];
            {
                const ulonglong2* bv = reinterpret_cast<const ulonglong2*>(&smem[OFF_B1 + fl * 16]);
                #pragma unroll
                for (int j = 0; j < 4; ++j) {
                    ulonglong2 v = bv[j];
                    h1A[2*j] = v.x; h1A[2*j+1] = v.y;
                    h1B[2*j] = v.x; h1B[2*j+1] = v.y;
                }
            }
            #pragma unroll
            for (int d = 0; d < 5; ++d) {
                const ulonglong2* wv = reinterpret_cast<const ulonglong2*>(&smem[OFF_W1 + fl * 80 + d * 16]);
                #pragma unroll
                for (int j = 0; j < 4; ++j) {
                    ulonglong2 v = wv[j];
                    fma2(h1A[2*j],   v.x, ydA[d]);
                    fma2(h1A[2*j+1], v.y, ydA[d]);
                    fma2(h1B[2*j],   v.x, ydB[d]);
                    fma2(h1B[2*j+1], v.y, ydB[d]);
                }
            }

            float hA[16], hB[16];
            #pragma unroll
            for (int j = 0; j < 8; ++j) {
                unpack2(h1A[j], hA[2*j], hA[2*j+1]);
                unpack2(h1B[j], hB[2*j], hB[2*j+1]);
            }

            // ---- layer 2 (packed): outputs 30,31 = padding, never consumed ----
            unsigned long long sA[16], sB[16];
            {
                const ulonglong2* bv = reinterpret_cast<const ulonglong2*>(&smem[OFF_B2 + fl * 32]);
                #pragma unroll
                for (int j = 0; j < 8; ++j) {
                    ulonglong2 v = bv[j];
                    sA[2*j] = v.x; sA[2*j+1] = v.y;
                    sB[2*j] = v.x; sB[2*j+1] = v.y;
                }
            }
            #pragma unroll
            for (int h = 0; h < 15; ++h) {
                unsigned long long hhA = pack2(hA[h], hA[h]);
                unsigned long long hhB = pack2(hB[h], hB[h]);
                const ulonglong2* wv = reinterpret_cast<const ulonglong2*>(&smem[OFF_W2 + fl * 480 + h * 32]);
                #pragma unroll
                for (int j = 0; j < 8; ++j) {
                    ulonglong2 v = wv[j];
                    fma2(sA[2*j],   v.x, hhA);
                    fma2(sA[2*j+1], v.y, hhA);
                    fma2(sB[2*j],   v.x, hhB);
                    fma2(sB[2*j+1], v.y, hhB);
                }
            }

            // ---- relu + dot with w3 slice ----
            const float4* w3v = reinterpret_cast<const float4*>(&smem[OFF_W3 + fl * 32]);
            #pragma unroll
            for (int j = 0; j < 7; ++j) {
                float4 v = w3v[j];
                float a0, a1, a2, a3, b0, b1_, b2_, b3_;
                unpack2(sA[2*j],   a0, a1);
                unpack2(sA[2*j+1], a2, a3);
                unpack2(sB[2*j],   b0, b1_);
                unpack2(sB[2*j+1], b2_, b3_);
                accA0 = fmaf(fmaxf(a0, 0.f), v.x, accA0);
                accA1 = fmaf(fmaxf(a1, 0.f), v.y, accA1);
                accA0 = fmaf(fmaxf(a2, 0.f), v.z, accA0);
                accA1 = fmaf(fmaxf(a3, 0.f), v.w, accA1);
                accB0 = fmaf(fmaxf(b0,  0.f), v.x, accB0);
                accB1 = fmaf(fmaxf(b1_, 0.f), v.y, accB1);
                accB0 = fmaf(fmaxf(b2_, 0.f), v.z, accB0);
                accB1 = fmaf(fmaxf(b3_, 0.f), v.w, accB1);
            }
            {
                float4 v = w3v[7];
                float a0, a1, b0, b1_;
                unpack2(sA[14], a0, a1);
                unpack2(sB[14], b0, b1_);
                accA0 = fmaf(fmaxf(a0, 0.f), v.x, accA0);
                accA1 = fmaf(fmaxf(a1, 0.f), v.y, accA1);
                accB0 = fmaf(fmaxf(b0,  0.f), v.x, accB0);
                accB1 = fmaf(fmaxf(b1_, 0.f), v.y, accB1);
            }
        }
    }

    // combine halves: out pre-initialized to b3; REDG to distinct addresses is ~free
    atomicAdd(out + rowA, accA0 + accA1);
    atomicAdd(out + rowB, accB0 + accB1);
}

extern "C" void kernel_launch(void* const* d_in, const int* in_sizes, int n_in,
                              void* d_out, int out_size)
{
    const float* y  = (const float*)d_in[0];
    const float* W1 = (const float*)d_in[1];
    const float* b1 = (const float*)d_in[2];
    const float* W2 = (const float*)d_in[3];
    const float* b2 = (const float*)d_in[4];
    const float* W3 = (const float*)d_in[5];
    const float* b3 = (const float*)d_in[6];
    float* out = (float*)d_out;

    static bool attr_set = false;
    cudaFuncSetAttribute(mlp_fused_kernel, cudaFuncAttributeMaxDynamicSharedMemorySize, SMEM_BYTES);

    init_out_kernel<<<B / TPB, TPB>>>(b3, out);
    mlp_fused_kernel<<<GRID, TPB, SMEM_BYTES>>>(y, W1, b1, W2, b2, W3, out);
    (void)attr_set;
}

// round 4
// speedup vs baseline: 1.6813x; 1.2119x over previous
#include <cuda_runtime.h>

constexpr int B    = 32768;
constexpr int S    = 4;            // feature quarters
constexpr int FQ   = 50;           // features per quarter
constexpr int FC   = 5;            // features per smem chunk
constexpr int NCH  = FQ / FC;      // 10 chunks

constexpr int TPB  = 256;
constexpr int RB   = 74;           // row-blocks (74*2 blocks per SM over 148 SMs)
constexpr int GRID = S * RB;       // 296
constexpr int SLOT = RB * TPB;     // 18944 (R=2: rowB = rowA + SLOT)

constexpr int YPITCH = 27;         // 25 data + pad, odd -> conflict-free

// smem layout (float offsets, all 16B aligned)
constexpr int OFF_YA = 0;
constexpr int OFF_YB = OFF_YA + TPB * YPITCH;   // 6912
constexpr int OFF_W1 = OFF_YB + TPB * YPITCH;   // 13824  [f][d][16]
constexpr int OFF_B1 = OFF_W1 + FC * 5 * 16;    // 14224  [f][16]
constexpr int OFF_W2 = OFF_B1 + FC * 16;        // 14304  [f][h][32]
constexpr int OFF_B2 = OFF_W2 + FC * 15 * 32;   // 16704  [f][32]
constexpr int OFF_W3 = OFF_B2 + FC * 32;        // 16864  [f][32]
constexpr int SMEM_FLOATS = OFF_W3 + FC * 32;   // 17024
constexpr int SMEM_BYTES  = SMEM_FLOATS * 4;    // 68096 B (x2 blocks = 136KB <= 228KB)

typedef unsigned long long u64;

__device__ __forceinline__ u64 pack2(float lo, float hi) {
    u64 r; asm("mov.b64 %0, {%1, %2};" : "=l"(r) : "f"(lo), "f"(hi)); return r;
}
__device__ __forceinline__ void unpack2(u64 v, float& lo, float& hi) {
    asm("mov.b64 {%0, %1}, %2;" : "=f"(lo), "=f"(hi) : "l"(v));
}
__device__ __forceinline__ void fma2(u64& d, u64 a, u64 b) {
    asm("fma.rn.f32x2 %0, %1, %2, %0;" : "+l"(d) : "l"(a), "l"(b));
}

__global__ void init_out_kernel(const float* __restrict__ b3, float* __restrict__ out) {
    int i = blockIdx.x * blockDim.x + threadIdx.x;
    out[i] = __ldg(b3);
}

__global__ __launch_bounds__(TPB, 2)
void mlp_fused_kernel(const float* __restrict__ y,
                      const float* __restrict__ W1,
                      const float* __restrict__ b1,
                      const float* __restrict__ W2,
                      const float* __restrict__ b2,
                      const float* __restrict__ W3,
                      float* __restrict__ out)
{
    extern __shared__ float smem[];

    const int tid = threadIdx.x;
    const int bq  = blockIdx.x / RB;          // feature quarter 0..3
    const int br  = blockIdx.x % RB;          // row block 0..73

    const int rA0  = br * TPB;
    const int rB0  = rA0 + SLOT;
    const int rowA = rA0 + tid;               // < 18944 < B, always valid
    const int rowBr = rB0 + tid;
    const bool validB = (rowBr < B);

    float accA0 = 0.f, accA1 = 0.f, accB0 = 0.f, accB1 = 0.f;

    for (int c = 0; c < NCH; ++c) {
        const int f0 = bq * FQ + c * FC;

        __syncthreads();

        // ---- stage y tiles (both row groups) ----
        for (int i = tid; i < TPB * 25; i += TPB) {
            int r = i / 25, cc = i % 25;
            int ga = rA0 + r;
            smem[OFF_YA + r * YPITCH + cc] = __ldg(y + (size_t)ga * 1000 + f0 * 5 + cc);
            int gb = rB0 + r; gb = (gb < B) ? gb : (B - 1);
            smem[OFF_YB + r * YPITCH + cc] = __ldg(y + (size_t)gb * 1000 + f0 * 5 + cc);
        }
        // ---- stage weights (padded) ----
        for (int i = tid; i < FC * 75; i += TPB) {
            int f = i / 75, r = i % 75, d = r / 15, h = r % 15;
            smem[OFF_W1 + f * 80 + d * 16 + h] = W1[f0 * 75 + i];
        }
        for (int i = tid; i < FC * 15; i += TPB) {
            int f = i / 15, h = i % 15;
            smem[OFF_B1 + f * 16 + h] = b1[f0 * 15 + i];
        }
        for (int i = tid; i < FC * 450; i += TPB) {
            int f = i / 450, r = i % 450, h = r / 30, o = r % 30;
            smem[OFF_W2 + f * 480 + h * 32 + o] = W2[f0 * 450 + i];
        }
        for (int i = tid; i < FC * 30; i += TPB) {
            int f = i / 30, o = i % 30;
            smem[OFF_B2 + f * 32 + o] = b2[f0 * 30 + i];
            smem[OFF_W3 + f * 32 + o] = W3[f0 * 30 + i];
        }
        __syncthreads();

        #pragma unroll 1
        for (int fl = 0; fl < FC; ++fl) {
            // y from smem (conflict-free: pitch 27)
            const float* yAp = &smem[OFF_YA + tid * YPITCH + fl * 5];
            const float* yBp = &smem[OFF_YB + tid * YPITCH + fl * 5];
            u64 ydA[5], ydB[5];
            #pragma unroll
            for (int d = 0; d < 5; ++d) {
                float va = yAp[d], vb = yBp[d];
                ydA[d] = pack2(va, va);
                ydB[d] = pack2(vb, vb);
            }

            // ---- layer 1 (packed): 8 pairs, pair-7 hi = padding garbage ----
            u64 h1A[8], h1B[8];
            {
                const ulonglong2* bv = reinterpret_cast<const ulonglong2*>(&smem[OFF_B1 + fl * 16]);
                #pragma unroll
                for (int j = 0; j < 4; ++j) {
                    ulonglong2 v = bv[j];
                    h1A[2*j] = v.x; h1A[2*j+1] = v.y;
                    h1B[2*j] = v.x; h1B[2*j+1] = v.y;
                }
            }
            #pragma unroll
            for (int d = 0; d < 5; ++d) {
                const ulonglong2* wv = reinterpret_cast<const ulonglong2*>(&smem[OFF_W1 + fl * 80 + d * 16]);
                #pragma unroll
                for (int j = 0; j < 4; ++j) {
                    ulonglong2 v = wv[j];
                    fma2(h1A[2*j],   v.x, ydA[d]);
                    fma2(h1A[2*j+1], v.y, ydA[d]);
                    fma2(h1B[2*j],   v.x, ydB[d]);
                    fma2(h1B[2*j+1], v.y, ydB[d]);
                }
            }

            float hA[15], hB[15], dumA, dumB;
            #pragma unroll
            for (int j = 0; j < 7; ++j) {
                unpack2(h1A[j], hA[2*j], hA[2*j+1]);
                unpack2(h1B[j], hB[2*j], hB[2*j+1]);
            }
            unpack2(h1A[7], hA[14], dumA);
            unpack2(h1B[7], hB[14], dumB);

            // ======== layer 2, pass 1: output pairs 0..7 (outputs 0..15) ========
            {
                u64 sA[8], sB[8];
                const ulonglong2* bv = reinterpret_cast<const ulonglong2*>(&smem[OFF_B2 + fl * 32]);
                #pragma unroll
                for (int j = 0; j < 4; ++j) {
                    ulonglong2 v = bv[j];
                    sA[2*j] = v.x; sA[2*j+1] = v.y;
                    sB[2*j] = v.x; sB[2*j+1] = v.y;
                }
                #pragma unroll
                for (int h = 0; h < 15; ++h) {
                    u64 hhA = pack2(hA[h], hA[h]);
                    u64 hhB = pack2(hB[h], hB[h]);
                    const ulonglong2* wv = reinterpret_cast<const ulonglong2*>(&smem[OFF_W2 + fl * 480 + h * 32]);
                    #pragma unroll
                    for (int j = 0; j < 4; ++j) {
                        ulonglong2 v = wv[j];
                        fma2(sA[2*j],   v.x, hhA);
                        fma2(sA[2*j+1], v.y, hhA);
                        fma2(sB[2*j],   v.x, hhB);
                        fma2(sB[2*j+1], v.y, hhB);
                    }
                }
                const float4* w3v = reinterpret_cast<const float4*>(&smem[OFF_W3 + fl * 32]);
                #pragma unroll
                for (int j = 0; j < 4; ++j) {
                    float4 v = w3v[j];
                    float a0, a1, a2, a3, b0, b1_, b2_, b3_;
                    unpack2(sA[2*j],   a0, a1);
                    unpack2(sA[2*j+1], a2, a3);
                    unpack2(sB[2*j],   b0, b1_);
                    unpack2(sB[2*j+1], b2_, b3_);
                    accA0 = fmaf(fmaxf(a0, 0.f), v.x, accA0);
                    accA1 = fmaf(fmaxf(a1, 0.f), v.y, accA1);
                    accA0 = fmaf(fmaxf(a2, 0.f), v.z, accA0);
                    accA1 = fmaf(fmaxf(a3, 0.f), v.w, accA1);
                    accB0 = fmaf(fmaxf(b0,  0.f), v.x, accB0);
                    accB1 = fmaf(fmaxf(b1_, 0.f), v.y, accB1);
                    accB0 = fmaf(fmaxf(b2_, 0.f), v.z, accB0);
                    accB1 = fmaf(fmaxf(b3_, 0.f), v.w, accB1);
                }
            }

            // ======== layer 2, pass 2: output pairs 8..14 (outputs 16..29) ========
            {
                u64 sA[7], sB[7];
                {
                    const ulonglong2* bv = reinterpret_cast<const ulonglong2*>(&smem[OFF_B2 + fl * 32 + 16]);
                    ulonglong2 v0 = bv[0], v1 = bv[1], v2 = bv[2];
                    u64 v3 = *reinterpret_cast<const u64*>(&smem[OFF_B2 + fl * 32 + 28]);
                    sA[0]=v0.x; sA[1]=v0.y; sA[2]=v1.x; sA[3]=v1.y; sA[4]=v2.x; sA[5]=v2.y; sA[6]=v3;
                    sB[0]=v0.x; sB[1]=v0.y; sB[2]=v1.x; sB[3]=v1.y; sB[4]=v2.x; sB[5]=v2.y; sB[6]=v3;
                }
                #pragma unroll
                for (int h = 0; h < 15; ++h) {
                    u64 hhA = pack2(hA[h], hA[h]);
                    u64 hhB = pack2(hB[h], hB[h]);
                    const ulonglong2* wv = reinterpret_cast<const ulonglong2*>(&smem[OFF_W2 + fl * 480 + h * 32 + 16]);
                    ulonglong2 v0 = wv[0], v1 = wv[1], v2 = wv[2];
                    u64 v3 = *reinterpret_cast<const u64*>(&smem[OFF_W2 + fl * 480 + h * 32 + 28]);
                    fma2(sA[0], v0.x, hhA); fma2(sA[1], v0.y, hhA);
                    fma2(sA[2], v1.x, hhA); fma2(sA[3], v1.y, hhA);
                    fma2(sA[4], v2.x, hhA); fma2(sA[5], v2.y, hhA);
                    fma2(sA[6], v3,   hhA);
                    fma2(sB[0], v0.x, hhB); fma2(sB[1], v0.y, hhB);
                    fma2(sB[2], v1.x, hhB); fma2(sB[3], v1.y, hhB);
                    fma2(sB[4], v2.x, hhB); fma2(sB[5], v2.y, hhB);
                    fma2(sB[6], v3,   hhB);
                }
                const float2* w3v = reinterpret_cast<const float2*>(&smem[OFF_W3 + fl * 32 + 16]);
                #pragma unroll
                for (int j = 0; j < 7; ++j) {
                    float2 v = w3v[j];
                    float a0, a1, b0, b1_;
                    unpack2(sA[j], a0, a1);
                    unpack2(sB[j], b0, b1_);
                    accA0 = fmaf(fmaxf(a0, 0.f), v.x, accA0);
                    accA1 = fmaf(fmaxf(a1, 0.f), v.y, accA1);
                    accB0 = fmaf(fmaxf(b0,  0.f), v.x, accB0);
                    accB1 = fmaf(fmaxf(b1_, 0.f), v.y, accB1);
                }
            }
        }
    }

    // combine feature-quarter partials; out pre-initialized to b3
    atomicAdd(out + rowA, accA0 + accA1);
    if (validB) atomicAdd(out + rowBr, accB0 + accB1);
}

extern "C" void kernel_launch(void* const* d_in, const int* in_sizes, int n_in,
                              void* d_out, int out_size)
{
    const float* y  = (const float*)d_in[0];
    const float* W1 = (const float*)d_in[1];
    const float* b1 = (const float*)d_in[2];
    const float* W2 = (const float*)d_in[3];
    const float* b2 = (const float*)d_in[4];
    const float* W3 = (const float*)d_in[5];
    const float* b3 = (const float*)d_in[6];
    float* out = (float*)d_out;

    cudaFuncSetAttribute(mlp_fused_kernel, cudaFuncAttributeMaxDynamicSharedMemorySize, SMEM_BYTES);

    init_out_kernel<<<B / TPB, TPB>>>(b3, out);
    mlp_fused_kernel<<<GRID, TPB, SMEM_BYTES>>>(y, W1, b1, W2, b2, W3, out);
}